// round 9
// baseline (speedup 1.0000x reference)
#include <cuda_runtime.h>
#include <cstdint>

// ============================================================================
// PTV3_CPE: sparse-conv(27-tap gather GEMM) + Linear + LayerNorm, fused.
// Plain-sm_103 path: mma.sync.m16n8k8.tf32 + ldmatrix + cp.async.
// R8: warp-specialized producer/consumer pipeline with named barriers.
//     8 MMA warps (128x64-col tiles each) + 8 copy warps, 3-deep ring.
// ============================================================================

#define CH 128
#define KT 27
#define TILE_M 128
#define NSTAGE 3
#define NSTAGES_TOTAL (2 * KT)  // (tap, K-half) stages = 54
#define MAXN 200000

__device__ float g_feats[MAXN * CH];       // tf32-pre-rounded feats (102.4 MB bss)
__device__ float g_Wm[KT * 2 * 128 * 64];  // folded weights, stage layout [k][h][n][kk]
__device__ float g_fb[CH];                 // folded bias

// ---------------------------- helpers --------------------------------------
__device__ __forceinline__ uint32_t smem_u32(const void* p) {
    uint32_t a;
    asm("{ .reg .u64 t; cvta.to.shared.u64 t, %1; cvt.u32.u64 %0, t; }" : "=r"(a) : "l"(p));
    return a;
}
__device__ __forceinline__ uint32_t tf32r(float f) {
    uint32_t r;
    asm("cvt.rna.tf32.f32 %0, %1;" : "=r"(r) : "f"(f));
    return r;
}
__device__ __forceinline__ void cpasync16(uint32_t dst, const void* src) {
    asm volatile("cp.async.cg.shared.global [%0], [%1], 16;" :: "r"(dst), "l"(src) : "memory");
}
__device__ __forceinline__ void cp_commit() {
    asm volatile("cp.async.commit_group;" ::: "memory");
}
__device__ __forceinline__ void cp_wait1() {
    asm volatile("cp.async.wait_group 1;" ::: "memory");
}
__device__ __forceinline__ void cp_wait0() {
    asm volatile("cp.async.wait_group 0;" ::: "memory");
}
__device__ __forceinline__ void bar_sync(int id) {
    asm volatile("bar.sync %0, 512;" :: "r"(id) : "memory");
}
__device__ __forceinline__ void bar_arrive(int id) {
    asm volatile("bar.arrive %0, 512;" :: "r"(id) : "memory");
}
__device__ __forceinline__ void ldsm_x4(uint32_t& r0, uint32_t& r1, uint32_t& r2, uint32_t& r3,
                                        uint32_t addr) {
    asm volatile("ldmatrix.sync.aligned.m8n8.x4.shared.b16 {%0,%1,%2,%3}, [%4];"
                 : "=r"(r0), "=r"(r1), "=r"(r2), "=r"(r3) : "r"(addr));
}
__device__ __forceinline__ void mma_tf32(float* d, uint32_t a0, uint32_t a1, uint32_t a2,
                                         uint32_t a3, uint32_t b0, uint32_t b1) {
    asm volatile(
        "mma.sync.aligned.m16n8k8.row.col.f32.tf32.tf32.f32 "
        "{%0,%1,%2,%3}, {%4,%5,%6,%7}, {%8,%9}, {%0,%1,%2,%3};"
        : "+f"(d[0]), "+f"(d[1]), "+f"(d[2]), "+f"(d[3])
        : "r"(a0), "r"(a1), "r"(a2), "r"(a3), "r"(b0), "r"(b1));
}

// ---------------------- one-time prep kernels ------------------------------
__global__ __launch_bounds__(256) void preround_kernel(const float4* __restrict__ in, int n4) {
    int i = blockIdx.x * 256 + threadIdx.x;
    if (i < n4) {
        float4 v = in[i];
        float4 o;
        o.x = __uint_as_float(tf32r(v.x));
        o.y = __uint_as_float(tf32r(v.y));
        o.z = __uint_as_float(tf32r(v.z));
        o.w = __uint_as_float(tf32r(v.w));
        ((float4*)g_feats)[i] = o;
    }
}

// g_Wm[k][ic>>6][oc][ic&63] = tf32(sum_j conv_w[k][ic][j] * lin_w[oc][j])
static constexpr int FOLD_SMEM = 2 * 128 * 33 * 16;

__global__ __launch_bounds__(256, 1) void fold_kernel(const float* __restrict__ conv_w,
                                                      const float* __restrict__ lin_w) {
    extern __shared__ float4 sm4[];
    float4* lw4 = sm4;
    float4* cw4 = sm4 + 128 * 33;
    int k = blockIdx.x;
    const float4* lws = (const float4*)lin_w;
    const float4* cws = (const float4*)(conv_w + (size_t)k * CH * CH);
    for (int q = threadIdx.x; q < 128 * 32; q += 256) {
        int row = q >> 5, c = q & 31;
        lw4[row * 33 + c] = lws[q];
        cw4[row * 33 + c] = cws[q];
    }
    __syncthreads();
    int tx = threadIdx.x & 15, ty = threadIdx.x >> 4;
    float acc[8][8];
#pragma unroll
    for (int o = 0; o < 8; o++)
#pragma unroll
        for (int i = 0; i < 8; i++) acc[o][i] = 0.f;
    for (int jc = 0; jc < 32; ++jc) {
        float4 a[8], b[8];
#pragma unroll
        for (int o = 0; o < 8; o++) a[o] = lw4[(ty + o * 16) * 33 + jc];
#pragma unroll
        for (int i = 0; i < 8; i++) b[i] = cw4[(tx + i * 16) * 33 + jc];
#pragma unroll
        for (int o = 0; o < 8; o++)
#pragma unroll
            for (int i = 0; i < 8; i++)
                acc[o][i] += a[o].x * b[i].x + a[o].y * b[i].y + a[o].z * b[i].z + a[o].w * b[i].w;
    }
#pragma unroll
    for (int o = 0; o < 8; o++) {
        int oc = ty + o * 16;
#pragma unroll
        for (int i = 0; i < 8; i++) {
            int ic = tx + i * 16;
            g_Wm[(((size_t)k * 2 + (ic >> 6)) * 128 + oc) * 64 + (ic & 63)] =
                __uint_as_float(tf32r(acc[o][i]));
        }
    }
}

__global__ void bias_kernel(const float* __restrict__ lin_w, const float* __restrict__ conv_b,
                            const float* __restrict__ lin_b) {
    int c = threadIdx.x;
    float s = lin_b[c];
    for (int j = 0; j < CH; j++) s += lin_w[c * CH + j] * conv_b[j];
    g_fb[c] = s;
}

// ---------------------------- main fused kernel ----------------------------
// SMEM: s_idx[27][128] | fb/lnw/lnb | 3 stage bufs {A 32KB | B 32KB}
static constexpr int IDX_OFF = 0;
static constexpr int FB_OFF = 13824;
static constexpr int LNW_OFF = 14336;
static constexpr int LNB_OFF = 14848;
static constexpr int STAGE_OFF = 16384;
static constexpr int STAGE_BYTES = 65536;  // 32KB A + 32KB B
static constexpr int MAIN_SMEM = STAGE_OFF + NSTAGE * STAGE_BYTES;  // 212992

// named barrier ids: full[b] = 1+b, empty[b] = 4+b
__global__ __launch_bounds__(512, 1) void ptv3_main(const int* __restrict__ nbr,
                                                    const float* __restrict__ ln_w,
                                                    const float* __restrict__ ln_b,
                                                    float* __restrict__ out, int n) {
    extern __shared__ char sm[];
    int* s_idx = (int*)(sm + IDX_OFF);
    float* s_fb = (float*)(sm + FB_OFF);
    float* s_lnw = (float*)(sm + LNW_OFF);
    float* s_lnb = (float*)(sm + LNB_OFF);
    char* s_stage = sm + STAGE_OFF;

    const int tid = threadIdx.x;
    const int base = blockIdx.x * TILE_M;
    const int lane = tid & 31, wid = tid >> 5;
    const int quad = lane >> 2, four = lane & 3;

    for (int q = tid; q < TILE_M * KT; q += 512) {
        int r = q / KT, k = q % KT;
        int g = base + r;
        s_idx[k * TILE_M + r] = (g < n) ? nbr[(size_t)base * KT + q] : 0;
    }
    if (tid < CH) {
        s_fb[tid] = g_fb[tid];
        s_lnw[tid] = ln_w[tid];
        s_lnb[tid] = ln_b[tid];
    }
    __syncthreads();

    const uint32_t stage_u32 = smem_u32(s_stage);

    float acc[2][8][4];
#pragma unroll
    for (int tm = 0; tm < 2; tm++)
#pragma unroll
        for (int tn = 0; tn < 8; tn++)
#pragma unroll
            for (int i = 0; i < 4; i++) acc[tm][tn][i] = 0.f;

    const int wm = (wid & 3) * 32;   // consumer M offset (4 M-groups)
    const int wn = (wid >> 2) * 64;  // consumer N offset (2 N-groups)

    if (wid < 8) {
        // ======================= CONSUMERS (MMA) ============================
        const int a_r0 = wm + ((lane >> 3) & 1) * 8 + (lane & 7);  // + tm*16
        const int a_hi = lane >> 4;
        const int b_n0 = wn + (lane >> 4) * 8 + (lane & 7);        // + p*16
        const int b_kn = (lane >> 3) & 1;

        for (int s = 0; s < NSTAGES_TOTAL; ++s) {
            const int buf = s % NSTAGE;
            bar_sync(1 + buf);  // wait full
            const uint32_t Ab = stage_u32 + (uint32_t)buf * STAGE_BYTES;
            const uint32_t Bb = Ab + 32768u;

#pragma unroll
            for (int kt = 0; kt < 8; ++kt) {
                uint32_t bf[8][2];
#pragma unroll
                for (int p = 0; p < 4; ++p) {
                    const int nr = b_n0 + p * 16;
                    const int c = kt * 2 + b_kn;
                    ldsm_x4(bf[2 * p][0], bf[2 * p][1], bf[2 * p + 1][0], bf[2 * p + 1][1],
                            Bb + (uint32_t)nr * 256 + ((uint32_t)(c ^ (nr & 7)) << 4));
                }
#pragma unroll
                for (int tm = 0; tm < 2; ++tm) {
                    const int ar = a_r0 + tm * 16;
                    const int c = kt * 2 + a_hi;
                    uint32_t a0, a1, a2, a3;
                    ldsm_x4(a0, a1, a2, a3,
                            Ab + (uint32_t)ar * 256 + ((uint32_t)(c ^ (ar & 7)) << 4));
#pragma unroll
                    for (int tn = 0; tn < 8; ++tn)
                        mma_tf32(acc[tm][tn], a0, a1, a2, a3, bf[tn][0], bf[tn][1]);
                }
            }
            if (s + NSTAGE < NSTAGES_TOTAL) bar_arrive(4 + buf);  // signal empty
        }
    } else {
        // ======================= PRODUCERS (copy) ===========================
        const int ptid = tid - 256;                  // 0..255
        const int c_row = ptid >> 1, c_sub = ptid & 1;  // 2 thr/row, 8 chunks each
        const uint32_t a_dst0 = stage_u32 + (uint32_t)c_row * 256;
        const uint32_t b_dst0 = stage_u32 + 32768u + (uint32_t)c_row * 256;

        auto issue_stage = [&](int s) {
            const int k = s >> 1, h = s & 1, buf = s % NSTAGE;
            const uint32_t off = (uint32_t)buf * STAGE_BYTES;
            const float* asrc =
                g_feats + (size_t)s_idx[k * TILE_M + c_row] * CH + h * 64 + c_sub * 32;
#pragma unroll
            for (int j = 0; j < 8; ++j) {
                int c = c_sub * 8 + j;
                cpasync16(a_dst0 + off + ((uint32_t)(c ^ (c_row & 7)) << 4), asrc + j * 4);
            }
            const float* bsrc =
                g_Wm + (((size_t)k * 2 + h) * 128 + c_row) * 64 + c_sub * 32;
#pragma unroll
            for (int j = 0; j < 8; ++j) {
                int c = c_sub * 8 + j;
                cpasync16(b_dst0 + off + ((uint32_t)(c ^ (c_row & 7)) << 4), bsrc + j * 4);
            }
            cp_commit();
        };

        issue_stage(0);
        issue_stage(1);
        for (int s = 0; s < NSTAGES_TOTAL; ++s) {
            if (s + 1 < NSTAGES_TOTAL) cp_wait1(); else cp_wait0();  // group s landed
            bar_arrive(1 + s % NSTAGE);  // signal full
            if (s + 2 < NSTAGES_TOTAL) {
                const int nbuf = (s + 2) % NSTAGE;
                if (s + 2 >= NSTAGE) bar_sync(4 + nbuf);  // wait empty
                issue_stage(s + 2);
            }
        }
    }

    // ---- epilogue: stage accumulators, LayerNorm, store ----
    __syncthreads();
    float* stg = (float*)s_stage;  // [128][132]
    if (wid < 8) {
#pragma unroll
        for (int tm = 0; tm < 2; ++tm) {
            const int r = wm + tm * 16 + quad;
#pragma unroll
            for (int tn = 0; tn < 8; ++tn) {
                const int col = wn + tn * 8 + 2 * four;
                stg[r * 132 + col] = acc[tm][tn][0];
                stg[r * 132 + col + 1] = acc[tm][tn][1];
                stg[(r + 8) * 132 + col] = acc[tm][tn][2];
                stg[(r + 8) * 132 + col + 1] = acc[tm][tn][3];
            }
        }
    }
    __syncthreads();

    const int row = tid >> 2, qtr = tid & 3;
    const int c0 = qtr * 32;
    float sum = 0.f, sq = 0.f;
#pragma unroll
    for (int i = 0; i < 32; ++i) {
        float v = stg[row * 132 + c0 + i] + s_fb[c0 + i];
        sum += v;
        sq += v * v;
    }
    sum += __shfl_xor_sync(0xFFFFFFFFu, sum, 1);
    sq += __shfl_xor_sync(0xFFFFFFFFu, sq, 1);
    sum += __shfl_xor_sync(0xFFFFFFFFu, sum, 2);
    sq += __shfl_xor_sync(0xFFFFFFFFu, sq, 2);
    const float mu = sum * (1.f / 128.f);
    const float var = sq * (1.f / 128.f) - mu * mu;
    const float rs = rsqrtf(var + 1e-5f);

    const int grow = base + row;
    if (grow < n) {
        float4* orow = (float4*)(out + (size_t)grow * CH + c0);
#pragma unroll
        for (int q = 0; q < 8; ++q) {
            float4 o;
            const int c = c0 + q * 4;
            o.x = (stg[row * 132 + c + 0] + s_fb[c + 0] - mu) * rs * s_lnw[c + 0] + s_lnb[c + 0];
            o.y = (stg[row * 132 + c + 1] + s_fb[c + 1] - mu) * rs * s_lnw[c + 1] + s_lnb[c + 1];
            o.z = (stg[row * 132 + c + 2] + s_fb[c + 2] - mu) * rs * s_lnw[c + 2] + s_lnb[c + 2];
            o.w = (stg[row * 132 + c + 3] + s_fb[c + 3] - mu) * rs * s_lnw[c + 3] + s_lnb[c + 3];
            orow[q] = o;
        }
    }
}

// ---------------------------- launcher -------------------------------------
extern "C" void kernel_launch(void* const* d_in, const int* in_sizes, int n_in,
                              void* d_out, int out_size) {
    const float* feats = (const float*)d_in[0];
    const int* nbr = (const int*)d_in[1];
    const float* conv_w = (const float*)d_in[2];
    const float* conv_b = (const float*)d_in[3];
    const float* lin_w = (const float*)d_in[4];
    const float* lin_b = (const float*)d_in[5];
    const float* ln_w = (const float*)d_in[6];
    const float* ln_b = (const float*)d_in[7];
    float* out = (float*)d_out;
    int n = in_sizes[0] / CH;

    cudaFuncSetAttribute(fold_kernel, cudaFuncAttributeMaxDynamicSharedMemorySize, FOLD_SMEM);
    cudaFuncSetAttribute(ptv3_main, cudaFuncAttributeMaxDynamicSharedMemorySize, MAIN_SMEM);

    int n4 = n * (CH / 4);
    preround_kernel<<<(n4 + 255) / 256, 256>>>((const float4*)feats, n4);
    fold_kernel<<<KT, 256, FOLD_SMEM>>>(conv_w, lin_w);
    bias_kernel<<<1, CH>>>(lin_w, conv_b, lin_b);
    int grid = (n + TILE_M - 1) / TILE_M;
    ptv3_main<<<grid, 512, MAIN_SMEM>>>(nbr, ln_w, ln_b, out, n);
}

// round 10
// speedup vs baseline: 1.5184x; 1.5184x over previous
#include <cuda_runtime.h>
#include <cstdint>

// ============================================================================
// PTV3_CPE: sparse-conv(27-tap gather GEMM) + Linear + LayerNorm, fused.
// Plain-sm_103 path: mma.sync.m16n8k8.tf32 + ldmatrix + cp.async.
// R9: 2 CTAs/SM (256 thr, K-quarter stages of 32 cols, 32KB stages, NSTAGE=3).
// ============================================================================

#define CH 128
#define KT 27
#define TILE_M 128
#define NSTAGE 3
#define NSTAGES_TOTAL (4 * KT)  // (tap, K-quarter) stages = 108
#define MAXN 200000

__device__ float g_feats[MAXN * CH];       // tf32-pre-rounded feats (102.4 MB bss)
__device__ float g_Wm[KT * 4 * 128 * 32];  // folded weights, stage layout [k][q][oc][icq]
__device__ float g_fb[CH];                 // folded bias

// ---------------------------- helpers --------------------------------------
__device__ __forceinline__ uint32_t smem_u32(const void* p) {
    uint32_t a;
    asm("{ .reg .u64 t; cvta.to.shared.u64 t, %1; cvt.u32.u64 %0, t; }" : "=r"(a) : "l"(p));
    return a;
}
__device__ __forceinline__ uint32_t tf32r(float f) {
    uint32_t r;
    asm("cvt.rna.tf32.f32 %0, %1;" : "=r"(r) : "f"(f));
    return r;
}
__device__ __forceinline__ void cpasync16(uint32_t dst, const void* src) {
    asm volatile("cp.async.cg.shared.global [%0], [%1], 16;" :: "r"(dst), "l"(src) : "memory");
}
__device__ __forceinline__ void cp_commit() {
    asm volatile("cp.async.commit_group;" ::: "memory");
}
__device__ __forceinline__ void cp_wait1() {
    asm volatile("cp.async.wait_group 1;" ::: "memory");
}
__device__ __forceinline__ void cp_wait0() {
    asm volatile("cp.async.wait_group 0;" ::: "memory");
}
__device__ __forceinline__ void ldsm_x4(uint32_t& r0, uint32_t& r1, uint32_t& r2, uint32_t& r3,
                                        uint32_t addr) {
    asm volatile("ldmatrix.sync.aligned.m8n8.x4.shared.b16 {%0,%1,%2,%3}, [%4];"
                 : "=r"(r0), "=r"(r1), "=r"(r2), "=r"(r3) : "r"(addr));
}
__device__ __forceinline__ void mma_tf32(float* d, uint32_t a0, uint32_t a1, uint32_t a2,
                                         uint32_t a3, uint32_t b0, uint32_t b1) {
    asm volatile(
        "mma.sync.aligned.m16n8k8.row.col.f32.tf32.tf32.f32 "
        "{%0,%1,%2,%3}, {%4,%5,%6,%7}, {%8,%9}, {%0,%1,%2,%3};"
        : "+f"(d[0]), "+f"(d[1]), "+f"(d[2]), "+f"(d[3])
        : "r"(a0), "r"(a1), "r"(a2), "r"(a3), "r"(b0), "r"(b1));
}

// ---------------------- one-time prep kernels ------------------------------
__global__ __launch_bounds__(256) void preround_kernel(const float4* __restrict__ in, int n4) {
    int i = blockIdx.x * 256 + threadIdx.x;
    if (i < n4) {
        float4 v = in[i];
        float4 o;
        o.x = __uint_as_float(tf32r(v.x));
        o.y = __uint_as_float(tf32r(v.y));
        o.z = __uint_as_float(tf32r(v.z));
        o.w = __uint_as_float(tf32r(v.w));
        ((float4*)g_feats)[i] = o;
    }
}

// g_Wm[k][ic>>5][oc][ic&31] = tf32(sum_j conv_w[k][ic][j] * lin_w[oc][j])
static constexpr int FOLD_SMEM = 2 * 128 * 33 * 16;

__global__ __launch_bounds__(256, 1) void fold_kernel(const float* __restrict__ conv_w,
                                                      const float* __restrict__ lin_w) {
    extern __shared__ float4 sm4[];
    float4* lw4 = sm4;
    float4* cw4 = sm4 + 128 * 33;
    int k = blockIdx.x;
    const float4* lws = (const float4*)lin_w;
    const float4* cws = (const float4*)(conv_w + (size_t)k * CH * CH);
    for (int q = threadIdx.x; q < 128 * 32; q += 256) {
        int row = q >> 5, c = q & 31;
        lw4[row * 33 + c] = lws[q];
        cw4[row * 33 + c] = cws[q];
    }
    __syncthreads();
    int tx = threadIdx.x & 15, ty = threadIdx.x >> 4;
    float acc[8][8];
#pragma unroll
    for (int o = 0; o < 8; o++)
#pragma unroll
        for (int i = 0; i < 8; i++) acc[o][i] = 0.f;
    for (int jc = 0; jc < 32; ++jc) {
        float4 a[8], b[8];
#pragma unroll
        for (int o = 0; o < 8; o++) a[o] = lw4[(ty + o * 16) * 33 + jc];
#pragma unroll
        for (int i = 0; i < 8; i++) b[i] = cw4[(tx + i * 16) * 33 + jc];
#pragma unroll
        for (int o = 0; o < 8; o++)
#pragma unroll
            for (int i = 0; i < 8; i++)
                acc[o][i] += a[o].x * b[i].x + a[o].y * b[i].y + a[o].z * b[i].z + a[o].w * b[i].w;
    }
#pragma unroll
    for (int o = 0; o < 8; o++) {
        int oc = ty + o * 16;
#pragma unroll
        for (int i = 0; i < 8; i++) {
            int ic = tx + i * 16;
            g_Wm[(((size_t)k * 4 + (ic >> 5)) * 128 + oc) * 32 + (ic & 31)] =
                __uint_as_float(tf32r(acc[o][i]));
        }
    }
}

__global__ void bias_kernel(const float* __restrict__ lin_w, const float* __restrict__ conv_b,
                            const float* __restrict__ lin_b) {
    int c = threadIdx.x;
    float s = lin_b[c];
    for (int j = 0; j < CH; j++) s += lin_w[c * CH + j] * conv_b[j];
    g_fb[c] = s;
}

// ---------------------------- main fused kernel ----------------------------
// SMEM: s_idx[27][128] | fb/lnw/lnb | 3 stage bufs {A 16KB | B 16KB}
// Rows are 128B (32 floats); 16B chunk c stored at (c ^ (row&7)).
static constexpr int IDX_OFF = 0;
static constexpr int FB_OFF = 13824;
static constexpr int LNW_OFF = 14336;
static constexpr int LNB_OFF = 14848;
static constexpr int STAGE_OFF = 15360;
static constexpr int STAGE_BYTES = 32768;  // 16KB A + 16KB B
static constexpr int MAIN_SMEM = STAGE_OFF + NSTAGE * STAGE_BYTES;  // 113664

__global__ __launch_bounds__(256, 2) void ptv3_main(const int* __restrict__ nbr,
                                                    const float* __restrict__ ln_w,
                                                    const float* __restrict__ ln_b,
                                                    float* __restrict__ out, int n) {
    extern __shared__ char sm[];
    int* s_idx = (int*)(sm + IDX_OFF);
    float* s_fb = (float*)(sm + FB_OFF);
    float* s_lnw = (float*)(sm + LNW_OFF);
    float* s_lnb = (float*)(sm + LNB_OFF);
    char* s_stage = sm + STAGE_OFF;

    const int tid = threadIdx.x;
    const int base = blockIdx.x * TILE_M;
    const int lane = tid & 31, wid = tid >> 5;
    const int quad = lane >> 2, four = lane & 3;
    const int wm = (wid & 3) * 32;   // 4 M-groups x 32 rows
    const int wn = (wid >> 2) * 64;  // 2 N-groups x 64 cols

    for (int q = tid; q < TILE_M * KT; q += 256) {
        int r = q / KT, k = q % KT;
        int g = base + r;
        s_idx[k * TILE_M + r] = (g < n) ? nbr[(size_t)base * KT + q] : 0;
    }
    if (tid < CH) {
        s_fb[tid] = g_fb[tid];
        s_lnw[tid] = ln_w[tid];
        s_lnb[tid] = ln_b[tid];
    }
    __syncthreads();

    // copy roles: 2 threads/row, each moves 4 A chunks + 4 B chunks (16B)
    const int c_row = tid >> 1, c_sub = tid & 1;
    const uint32_t stage_u32 = smem_u32(s_stage);
    const uint32_t a_dst0 = stage_u32 + (uint32_t)c_row * 128;
    const uint32_t b_dst0 = stage_u32 + 16384u + (uint32_t)c_row * 128;

    auto issue_stage = [&](int s) {
        const int k = s >> 2, q = s & 3, buf = s % NSTAGE;
        const uint32_t off = (uint32_t)buf * STAGE_BYTES;
        const float* asrc = g_feats + (size_t)s_idx[k * TILE_M + c_row] * CH + q * 32 + c_sub * 16;
#pragma unroll
        for (int j = 0; j < 4; ++j) {
            int c = c_sub * 4 + j;
            cpasync16(a_dst0 + off + ((uint32_t)(c ^ (c_row & 7)) << 4), asrc + j * 4);
        }
        const float* bsrc = g_Wm + (((size_t)k * 4 + q) * 128 + c_row) * 32 + c_sub * 16;
#pragma unroll
        for (int j = 0; j < 4; ++j) {
            int c = c_sub * 4 + j;
            cpasync16(b_dst0 + off + ((uint32_t)(c ^ (c_row & 7)) << 4), bsrc + j * 4);
        }
        cp_commit();
    };

    issue_stage(0);
    issue_stage(1);

    // LDSM lane addressing (proven)
    const int a_r0 = wm + ((lane >> 3) & 1) * 8 + (lane & 7);  // + tm*16
    const int a_hi = lane >> 4;
    const int b_n0 = wn + (lane >> 4) * 8 + (lane & 7);        // + p*16
    const int b_kn = (lane >> 3) & 1;

    float acc[2][8][4];
#pragma unroll
    for (int tm = 0; tm < 2; tm++)
#pragma unroll
        for (int tn = 0; tn < 8; tn++)
#pragma unroll
            for (int i = 0; i < 4; i++) acc[tm][tn][i] = 0.f;

    for (int s = 0; s < NSTAGES_TOTAL; ++s) {
        if (s + 1 < NSTAGES_TOTAL) cp_wait1(); else cp_wait0();
        __syncthreads();  // buffer (s+2)%3 is free, stage s is full
        if (s + 2 < NSTAGES_TOTAL) issue_stage(s + 2);

        const uint32_t Ab = stage_u32 + (uint32_t)(s % NSTAGE) * STAGE_BYTES;
        const uint32_t Bb = Ab + 16384u;

#pragma unroll
        for (int kt = 0; kt < 4; ++kt) {
            uint32_t bf[8][2];
#pragma unroll
            for (int p = 0; p < 4; ++p) {
                const int nr = b_n0 + p * 16;
                const int c = kt * 2 + b_kn;
                ldsm_x4(bf[2 * p][0], bf[2 * p][1], bf[2 * p + 1][0], bf[2 * p + 1][1],
                        Bb + (uint32_t)nr * 128 + ((uint32_t)(c ^ (nr & 7)) << 4));
            }
#pragma unroll
            for (int tm = 0; tm < 2; ++tm) {
                const int ar = a_r0 + tm * 16;
                const int c = kt * 2 + a_hi;
                uint32_t a0, a1, a2, a3;
                ldsm_x4(a0, a1, a2, a3,
                        Ab + (uint32_t)ar * 128 + ((uint32_t)(c ^ (ar & 7)) << 4));
#pragma unroll
                for (int tn = 0; tn < 8; ++tn)
                    mma_tf32(acc[tm][tn], a0, a1, a2, a3, bf[tn][0], bf[tn][1]);
            }
        }
    }

    // ---- epilogue: stage accumulators, LayerNorm, store ----
    __syncthreads();
    float* stg = (float*)s_stage;  // [128][132] = 67584B, fits 3x32KB region
#pragma unroll
    for (int tm = 0; tm < 2; ++tm) {
        const int r = wm + tm * 16 + quad;
#pragma unroll
        for (int tn = 0; tn < 8; ++tn) {
            const int col = wn + tn * 8 + 2 * four;
            stg[r * 132 + col] = acc[tm][tn][0];
            stg[r * 132 + col + 1] = acc[tm][tn][1];
            stg[(r + 8) * 132 + col] = acc[tm][tn][2];
            stg[(r + 8) * 132 + col + 1] = acc[tm][tn][3];
        }
    }
    __syncthreads();

    const int row = tid >> 1, half = tid & 1;
    const int c0 = half * 64;
    float sum = 0.f, sq = 0.f;
#pragma unroll 16
    for (int i = 0; i < 64; ++i) {
        float v = stg[row * 132 + c0 + i] + s_fb[c0 + i];
        sum += v;
        sq += v * v;
    }
    sum += __shfl_xor_sync(0xFFFFFFFFu, sum, 1);
    sq += __shfl_xor_sync(0xFFFFFFFFu, sq, 1);
    const float mu = sum * (1.f / 128.f);
    const float var = sq * (1.f / 128.f) - mu * mu;
    const float rs = rsqrtf(var + 1e-5f);

    const int grow = base + row;
    if (grow < n) {
        float4* orow = (float4*)(out + (size_t)grow * CH + c0);
#pragma unroll
        for (int q = 0; q < 16; ++q) {
            float4 o;
            const int c = c0 + q * 4;
            o.x = (stg[row * 132 + c + 0] + s_fb[c + 0] - mu) * rs * s_lnw[c + 0] + s_lnb[c + 0];
            o.y = (stg[row * 132 + c + 1] + s_fb[c + 1] - mu) * rs * s_lnw[c + 1] + s_lnb[c + 1];
            o.z = (stg[row * 132 + c + 2] + s_fb[c + 2] - mu) * rs * s_lnw[c + 2] + s_lnb[c + 2];
            o.w = (stg[row * 132 + c + 3] + s_fb[c + 3] - mu) * rs * s_lnw[c + 3] + s_lnb[c + 3];
            orow[q] = o;
        }
    }
}

// ---------------------------- launcher -------------------------------------
extern "C" void kernel_launch(void* const* d_in, const int* in_sizes, int n_in,
                              void* d_out, int out_size) {
    const float* feats = (const float*)d_in[0];
    const int* nbr = (const int*)d_in[1];
    const float* conv_w = (const float*)d_in[2];
    const float* conv_b = (const float*)d_in[3];
    const float* lin_w = (const float*)d_in[4];
    const float* lin_b = (const float*)d_in[5];
    const float* ln_w = (const float*)d_in[6];
    const float* ln_b = (const float*)d_in[7];
    float* out = (float*)d_out;
    int n = in_sizes[0] / CH;

    cudaFuncSetAttribute(fold_kernel, cudaFuncAttributeMaxDynamicSharedMemorySize, FOLD_SMEM);
    cudaFuncSetAttribute(ptv3_main, cudaFuncAttributeMaxDynamicSharedMemorySize, MAIN_SMEM);

    int n4 = n * (CH / 4);
    preround_kernel<<<(n4 + 255) / 256, 256>>>((const float4*)feats, n4);
    fold_kernel<<<KT, 256, FOLD_SMEM>>>(conv_w, lin_w);
    bias_kernel<<<1, CH>>>(lin_w, conv_b, lin_b);
    int grid = (n + TILE_M - 1) / TILE_M;
    ptv3_main<<<grid, 256, MAIN_SMEM>>>(nbr, ln_w, ln_b, out, n);
}

// round 11
// speedup vs baseline: 1.5185x; 1.0000x over previous
#include <cuda_runtime.h>
#include <cstdint>

// ============================================================================
// PTV3_CPE: sparse-conv(27-tap gather GEMM) + Linear + LayerNorm, fused.
// Plain-sm_103 path: mma.sync.m16n8k8.tf32 + ldmatrix + cp.async.
// R9: 2 CTAs/SM (256 thr, K-quarter stages of 32 cols, 32KB stages, NSTAGE=3).
// ============================================================================

#define CH 128
#define KT 27
#define TILE_M 128
#define NSTAGE 3
#define NSTAGES_TOTAL (4 * KT)  // (tap, K-quarter) stages = 108
#define MAXN 200000

__device__ float g_feats[MAXN * CH];       // tf32-pre-rounded feats (102.4 MB bss)
__device__ float g_Wm[KT * 4 * 128 * 32];  // folded weights, stage layout [k][q][oc][icq]
__device__ float g_fb[CH];                 // folded bias

// ---------------------------- helpers --------------------------------------
__device__ __forceinline__ uint32_t smem_u32(const void* p) {
    uint32_t a;
    asm("{ .reg .u64 t; cvta.to.shared.u64 t, %1; cvt.u32.u64 %0, t; }" : "=r"(a) : "l"(p));
    return a;
}
__device__ __forceinline__ uint32_t tf32r(float f) {
    uint32_t r;
    asm("cvt.rna.tf32.f32 %0, %1;" : "=r"(r) : "f"(f));
    return r;
}
__device__ __forceinline__ void cpasync16(uint32_t dst, const void* src) {
    asm volatile("cp.async.cg.shared.global [%0], [%1], 16;" :: "r"(dst), "l"(src) : "memory");
}
__device__ __forceinline__ void cp_commit() {
    asm volatile("cp.async.commit_group;" ::: "memory");
}
__device__ __forceinline__ void cp_wait1() {
    asm volatile("cp.async.wait_group 1;" ::: "memory");
}
__device__ __forceinline__ void cp_wait0() {
    asm volatile("cp.async.wait_group 0;" ::: "memory");
}
__device__ __forceinline__ void ldsm_x4(uint32_t& r0, uint32_t& r1, uint32_t& r2, uint32_t& r3,
                                        uint32_t addr) {
    asm volatile("ldmatrix.sync.aligned.m8n8.x4.shared.b16 {%0,%1,%2,%3}, [%4];"
                 : "=r"(r0), "=r"(r1), "=r"(r2), "=r"(r3) : "r"(addr));
}
__device__ __forceinline__ void mma_tf32(float* d, uint32_t a0, uint32_t a1, uint32_t a2,
                                         uint32_t a3, uint32_t b0, uint32_t b1) {
    asm volatile(
        "mma.sync.aligned.m16n8k8.row.col.f32.tf32.tf32.f32 "
        "{%0,%1,%2,%3}, {%4,%5,%6,%7}, {%8,%9}, {%0,%1,%2,%3};"
        : "+f"(d[0]), "+f"(d[1]), "+f"(d[2]), "+f"(d[3])
        : "r"(a0), "r"(a1), "r"(a2), "r"(a3), "r"(b0), "r"(b1));
}

// ---------------------- one-time prep kernels ------------------------------
__global__ __launch_bounds__(256) void preround_kernel(const float4* __restrict__ in, int n4) {
    int i = blockIdx.x * 256 + threadIdx.x;
    if (i < n4) {
        float4 v = in[i];
        float4 o;
        o.x = __uint_as_float(tf32r(v.x));
        o.y = __uint_as_float(tf32r(v.y));
        o.z = __uint_as_float(tf32r(v.z));
        o.w = __uint_as_float(tf32r(v.w));
        ((float4*)g_feats)[i] = o;
    }
}

// g_Wm[k][ic>>5][oc][ic&31] = tf32(sum_j conv_w[k][ic][j] * lin_w[oc][j])
static constexpr int FOLD_SMEM = 2 * 128 * 33 * 16;

__global__ __launch_bounds__(256, 1) void fold_kernel(const float* __restrict__ conv_w,
                                                      const float* __restrict__ lin_w) {
    extern __shared__ float4 sm4[];
    float4* lw4 = sm4;
    float4* cw4 = sm4 + 128 * 33;
    int k = blockIdx.x;
    const float4* lws = (const float4*)lin_w;
    const float4* cws = (const float4*)(conv_w + (size_t)k * CH * CH);
    for (int q = threadIdx.x; q < 128 * 32; q += 256) {
        int row = q >> 5, c = q & 31;
        lw4[row * 33 + c] = lws[q];
        cw4[row * 33 + c] = cws[q];
    }
    __syncthreads();
    int tx = threadIdx.x & 15, ty = threadIdx.x >> 4;
    float acc[8][8];
#pragma unroll
    for (int o = 0; o < 8; o++)
#pragma unroll
        for (int i = 0; i < 8; i++) acc[o][i] = 0.f;
    for (int jc = 0; jc < 32; ++jc) {
        float4 a[8], b[8];
#pragma unroll
        for (int o = 0; o < 8; o++) a[o] = lw4[(ty + o * 16) * 33 + jc];
#pragma unroll
        for (int i = 0; i < 8; i++) b[i] = cw4[(tx + i * 16) * 33 + jc];
#pragma unroll
        for (int o = 0; o < 8; o++)
#pragma unroll
            for (int i = 0; i < 8; i++)
                acc[o][i] += a[o].x * b[i].x + a[o].y * b[i].y + a[o].z * b[i].z + a[o].w * b[i].w;
    }
#pragma unroll
    for (int o = 0; o < 8; o++) {
        int oc = ty + o * 16;
#pragma unroll
        for (int i = 0; i < 8; i++) {
            int ic = tx + i * 16;
            g_Wm[(((size_t)k * 4 + (ic >> 5)) * 128 + oc) * 32 + (ic & 31)] =
                __uint_as_float(tf32r(acc[o][i]));
        }
    }
}

__global__ void bias_kernel(const float* __restrict__ lin_w, const float* __restrict__ conv_b,
                            const float* __restrict__ lin_b) {
    int c = threadIdx.x;
    float s = lin_b[c];
    for (int j = 0; j < CH; j++) s += lin_w[c * CH + j] * conv_b[j];
    g_fb[c] = s;
}

// ---------------------------- main fused kernel ----------------------------
// SMEM: s_idx[27][128] | fb/lnw/lnb | 3 stage bufs {A 16KB | B 16KB}
// Rows are 128B (32 floats); 16B chunk c stored at (c ^ (row&7)).
static constexpr int IDX_OFF = 0;
static constexpr int FB_OFF = 13824;
static constexpr int LNW_OFF = 14336;
static constexpr int LNB_OFF = 14848;
static constexpr int STAGE_OFF = 15360;
static constexpr int STAGE_BYTES = 32768;  // 16KB A + 16KB B
static constexpr int MAIN_SMEM = STAGE_OFF + NSTAGE * STAGE_BYTES;  // 113664

__global__ __launch_bounds__(256, 2) void ptv3_main(const int* __restrict__ nbr,
                                                    const float* __restrict__ ln_w,
                                                    const float* __restrict__ ln_b,
                                                    float* __restrict__ out, int n) {
    extern __shared__ char sm[];
    int* s_idx = (int*)(sm + IDX_OFF);
    float* s_fb = (float*)(sm + FB_OFF);
    float* s_lnw = (float*)(sm + LNW_OFF);
    float* s_lnb = (float*)(sm + LNB_OFF);
    char* s_stage = sm + STAGE_OFF;

    const int tid = threadIdx.x;
    const int base = blockIdx.x * TILE_M;
    const int lane = tid & 31, wid = tid >> 5;
    const int quad = lane >> 2, four = lane & 3;
    const int wm = (wid & 3) * 32;   // 4 M-groups x 32 rows
    const int wn = (wid >> 2) * 64;  // 2 N-groups x 64 cols

    for (int q = tid; q < TILE_M * KT; q += 256) {
        int r = q / KT, k = q % KT;
        int g = base + r;
        s_idx[k * TILE_M + r] = (g < n) ? nbr[(size_t)base * KT + q] : 0;
    }
    if (tid < CH) {
        s_fb[tid] = g_fb[tid];
        s_lnw[tid] = ln_w[tid];
        s_lnb[tid] = ln_b[tid];
    }
    __syncthreads();

    // copy roles: 2 threads/row, each moves 4 A chunks + 4 B chunks (16B)
    const int c_row = tid >> 1, c_sub = tid & 1;
    const uint32_t stage_u32 = smem_u32(s_stage);
    const uint32_t a_dst0 = stage_u32 + (uint32_t)c_row * 128;
    const uint32_t b_dst0 = stage_u32 + 16384u + (uint32_t)c_row * 128;

    auto issue_stage = [&](int s) {
        const int k = s >> 2, q = s & 3, buf = s % NSTAGE;
        const uint32_t off = (uint32_t)buf * STAGE_BYTES;
        const float* asrc = g_feats + (size_t)s_idx[k * TILE_M + c_row] * CH + q * 32 + c_sub * 16;
#pragma unroll
        for (int j = 0; j < 4; ++j) {
            int c = c_sub * 4 + j;
            cpasync16(a_dst0 + off + ((uint32_t)(c ^ (c_row & 7)) << 4), asrc + j * 4);
        }
        const float* bsrc = g_Wm + (((size_t)k * 4 + q) * 128 + c_row) * 32 + c_sub * 16;
#pragma unroll
        for (int j = 0; j < 4; ++j) {
            int c = c_sub * 4 + j;
            cpasync16(b_dst0 + off + ((uint32_t)(c ^ (c_row & 7)) << 4), bsrc + j * 4);
        }
        cp_commit();
    };

    issue_stage(0);
    issue_stage(1);

    // LDSM lane addressing (proven)
    const int a_r0 = wm + ((lane >> 3) & 1) * 8 + (lane & 7);  // + tm*16
    const int a_hi = lane >> 4;
    const int b_n0 = wn + (lane >> 4) * 8 + (lane & 7);        // + p*16
    const int b_kn = (lane >> 3) & 1;

    float acc[2][8][4];
#pragma unroll
    for (int tm = 0; tm < 2; tm++)
#pragma unroll
        for (int tn = 0; tn < 8; tn++)
#pragma unroll
            for (int i = 0; i < 4; i++) acc[tm][tn][i] = 0.f;

    for (int s = 0; s < NSTAGES_TOTAL; ++s) {
        if (s + 1 < NSTAGES_TOTAL) cp_wait1(); else cp_wait0();
        __syncthreads();  // buffer (s+2)%3 is free, stage s is full
        if (s + 2 < NSTAGES_TOTAL) issue_stage(s + 2);

        const uint32_t Ab = stage_u32 + (uint32_t)(s % NSTAGE) * STAGE_BYTES;
        const uint32_t Bb = Ab + 16384u;

#pragma unroll
        for (int kt = 0; kt < 4; ++kt) {
            uint32_t bf[8][2];
#pragma unroll
            for (int p = 0; p < 4; ++p) {
                const int nr = b_n0 + p * 16;
                const int c = kt * 2 + b_kn;
                ldsm_x4(bf[2 * p][0], bf[2 * p][1], bf[2 * p + 1][0], bf[2 * p + 1][1],
                        Bb + (uint32_t)nr * 128 + ((uint32_t)(c ^ (nr & 7)) << 4));
            }
#pragma unroll
            for (int tm = 0; tm < 2; ++tm) {
                const int ar = a_r0 + tm * 16;
                const int c = kt * 2 + a_hi;
                uint32_t a0, a1, a2, a3;
                ldsm_x4(a0, a1, a2, a3,
                        Ab + (uint32_t)ar * 128 + ((uint32_t)(c ^ (ar & 7)) << 4));
#pragma unroll
                for (int tn = 0; tn < 8; ++tn)
                    mma_tf32(acc[tm][tn], a0, a1, a2, a3, bf[tn][0], bf[tn][1]);
            }
        }
    }

    // ---- epilogue: stage accumulators, LayerNorm, store ----
    __syncthreads();
    float* stg = (float*)s_stage;  // [128][132] = 67584B, fits 3x32KB region
#pragma unroll
    for (int tm = 0; tm < 2; ++tm) {
        const int r = wm + tm * 16 + quad;
#pragma unroll
        for (int tn = 0; tn < 8; ++tn) {
            const int col = wn + tn * 8 + 2 * four;
            stg[r * 132 + col] = acc[tm][tn][0];
            stg[r * 132 + col + 1] = acc[tm][tn][1];
            stg[(r + 8) * 132 + col] = acc[tm][tn][2];
            stg[(r + 8) * 132 + col + 1] = acc[tm][tn][3];
        }
    }
    __syncthreads();

    const int row = tid >> 1, half = tid & 1;
    const int c0 = half * 64;
    float sum = 0.f, sq = 0.f;
#pragma unroll 16
    for (int i = 0; i < 64; ++i) {
        float v = stg[row * 132 + c0 + i] + s_fb[c0 + i];
        sum += v;
        sq += v * v;
    }
    sum += __shfl_xor_sync(0xFFFFFFFFu, sum, 1);
    sq += __shfl_xor_sync(0xFFFFFFFFu, sq, 1);
    const float mu = sum * (1.f / 128.f);
    const float var = sq * (1.f / 128.f) - mu * mu;
    const float rs = rsqrtf(var + 1e-5f);

    const int grow = base + row;
    if (grow < n) {
        float4* orow = (float4*)(out + (size_t)grow * CH + c0);
#pragma unroll
        for (int q = 0; q < 16; ++q) {
            float4 o;
            const int c = c0 + q * 4;
            o.x = (stg[row * 132 + c + 0] + s_fb[c + 0] - mu) * rs * s_lnw[c + 0] + s_lnb[c + 0];
            o.y = (stg[row * 132 + c + 1] + s_fb[c + 1] - mu) * rs * s_lnw[c + 1] + s_lnb[c + 1];
            o.z = (stg[row * 132 + c + 2] + s_fb[c + 2] - mu) * rs * s_lnw[c + 2] + s_lnb[c + 2];
            o.w = (stg[row * 132 + c + 3] + s_fb[c + 3] - mu) * rs * s_lnw[c + 3] + s_lnb[c + 3];
            orow[q] = o;
        }
    }
}

// ---------------------------- launcher -------------------------------------
extern "C" void kernel_launch(void* const* d_in, const int* in_sizes, int n_in,
                              void* d_out, int out_size) {
    const float* feats = (const float*)d_in[0];
    const int* nbr = (const int*)d_in[1];
    const float* conv_w = (const float*)d_in[2];
    const float* conv_b = (const float*)d_in[3];
    const float* lin_w = (const float*)d_in[4];
    const float* lin_b = (const float*)d_in[5];
    const float* ln_w = (const float*)d_in[6];
    const float* ln_b = (const float*)d_in[7];
    float* out = (float*)d_out;
    int n = in_sizes[0] / CH;

    cudaFuncSetAttribute(fold_kernel, cudaFuncAttributeMaxDynamicSharedMemorySize, FOLD_SMEM);
    cudaFuncSetAttribute(ptv3_main, cudaFuncAttributeMaxDynamicSharedMemorySize, MAIN_SMEM);

    int n4 = n * (CH / 4);
    preround_kernel<<<(n4 + 255) / 256, 256>>>((const float4*)feats, n4);
    fold_kernel<<<KT, 256, FOLD_SMEM>>>(conv_w, lin_w);
    bias_kernel<<<1, CH>>>(lin_w, conv_b, lin_b);
    int grid = (n + TILE_M - 1) / TILE_M;
    ptv3_main<<<grid, 256, MAIN_SMEM>>>(nbr, ln_w, ln_b, out, n);
}

// round 12
// speedup vs baseline: 1.6166x; 1.0646x over previous
#include <cuda_runtime.h>
#include <cstdint>

// ============================================================================
// PTV3_CPE: sparse-conv(27-tap gather GEMM) + Linear + LayerNorm, fused.
// Plain-sm_103: mma.sync.m16n8k8.tf32 + ldmatrix + cp.async.bulk + mbarrier.
// R11: bulk-copy stages (16x fewer LSU ops), padded-row layout, 2 CTAs/SM.
// ============================================================================

#define CH 128
#define KT 27
#define TILE_M 128
#define NSTAGE 3
#define NSTAGES_TOTAL (4 * KT)  // (tap, K-quarter) stages = 108
#define MAXN 200000
#define MAXN2 200064  // padded to grid*TILE_M

#define ROWB 144                       // padded SMEM row stride (bytes)
#define A_BYTES (128 * ROWB)           // 18432
#define B_BYTES (128 * ROWB)           // 18432
#define STAGE_BYTES (A_BYTES + B_BYTES)
#define TX_BYTES (128 * 128 + 18432)   // actual bytes per stage = 34816

__device__ float g_feats[MAXN * CH];        // tf32-pre-rounded feats
__device__ float g_Wm[KT * 4 * 128 * 36];   // folded weights, padded stage rows
__device__ int g_idxT[KT * MAXN2];          // transposed neighbor idx [k][voxel]
__device__ float g_fb[CH];                  // folded bias

// ---------------------------- helpers --------------------------------------
__device__ __forceinline__ uint32_t smem_u32(const void* p) {
    uint32_t a;
    asm("{ .reg .u64 t; cvta.to.shared.u64 t, %1; cvt.u32.u64 %0, t; }" : "=r"(a) : "l"(p));
    return a;
}
__device__ __forceinline__ uint32_t tf32r(float f) {
    uint32_t r;
    asm("cvt.rna.tf32.f32 %0, %1;" : "=r"(r) : "f"(f));
    return r;
}
__device__ __forceinline__ void bulk_g2s(uint32_t dst, const void* src, uint32_t bytes,
                                         uint32_t mbar) {
    asm volatile(
        "cp.async.bulk.shared::cluster.global.mbarrier::complete_tx::bytes [%0], [%1], %2, [%3];"
        :: "r"(dst), "l"(src), "r"(bytes), "r"(mbar) : "memory");
}
#define MBAR_INIT(a, cnt) \
    asm volatile("mbarrier.init.shared.b64 [%0], %1;" :: "r"((uint32_t)(a)), "r"((uint32_t)(cnt)) : "memory")
#define MBAR_EXPECT(a, tx) \
    asm volatile("mbarrier.arrive.expect_tx.shared.b64 _, [%0], %1;" \
                 :: "r"((uint32_t)(a)), "r"((uint32_t)(tx)) : "memory")
#define MBAR_WAIT(a, par) do { \
    uint32_t _m = (uint32_t)(a); uint32_t _p = (uint32_t)(par); uint32_t _d; \
    asm volatile("{\n\t.reg .pred p;\n\t" \
        "mbarrier.try_wait.parity.acquire.cta.shared::cta.b64 p, [%1], %2;\n\t" \
        "selp.b32 %0, 1, 0, p;\n\t}" : "=r"(_d) : "r"(_m), "r"(_p) : "memory"); \
    if (!_d) { \
        asm volatile("{\n\t.reg .pred P1;\n\t" \
            "WL_%=:\n\t" \
            "mbarrier.try_wait.parity.acquire.cta.shared::cta.b64 P1, [%0], %1, 0x989680;\n\t" \
            "@P1 bra.uni WD_%=;\n\tbra.uni WL_%=;\n\tWD_%=:\n\t}" \
            :: "r"(_m), "r"(_p) : "memory"); \
    } \
} while (0)
#define FENCE_ASYNC() asm volatile("fence.proxy.async.shared::cta;" ::: "memory")

__device__ __forceinline__ void ldsm_x4(uint32_t& r0, uint32_t& r1, uint32_t& r2, uint32_t& r3,
                                        uint32_t addr) {
    asm volatile("ldmatrix.sync.aligned.m8n8.x4.shared.b16 {%0,%1,%2,%3}, [%4];"
                 : "=r"(r0), "=r"(r1), "=r"(r2), "=r"(r3) : "r"(addr));
}
__device__ __forceinline__ void mma_tf32(float* d, uint32_t a0, uint32_t a1, uint32_t a2,
                                         uint32_t a3, uint32_t b0, uint32_t b1) {
    asm volatile(
        "mma.sync.aligned.m16n8k8.row.col.f32.tf32.tf32.f32 "
        "{%0,%1,%2,%3}, {%4,%5,%6,%7}, {%8,%9}, {%0,%1,%2,%3};"
        : "+f"(d[0]), "+f"(d[1]), "+f"(d[2]), "+f"(d[3])
        : "r"(a0), "r"(a1), "r"(a2), "r"(a3), "r"(b0), "r"(b1));
}

// ---------------------- one-time prep kernels ------------------------------
__global__ __launch_bounds__(256) void preround_kernel(const float4* __restrict__ in, int n4) {
    int i = blockIdx.x * 256 + threadIdx.x;
    if (i < n4) {
        float4 v = in[i];
        float4 o;
        o.x = __uint_as_float(tf32r(v.x));
        o.y = __uint_as_float(tf32r(v.y));
        o.z = __uint_as_float(tf32r(v.z));
        o.w = __uint_as_float(tf32r(v.w));
        ((float4*)g_feats)[i] = o;
    }
}

__global__ __launch_bounds__(256) void idxt_kernel(const int* __restrict__ nbr, int n) {
    int v = blockIdx.x * 256 + threadIdx.x;
    if (v < MAXN2) {
#pragma unroll 1
        for (int k = 0; k < KT; ++k)
            g_idxT[(size_t)k * MAXN2 + v] = (v < n) ? nbr[(size_t)v * KT + k] : 0;
    }
}

// g_Wm[((k*4+q)*128 + oc)*36 + icq] = tf32(sum_j conv_w[k][ic][j]*lin_w[oc][j])
static constexpr int FOLD_SMEM = 2 * 128 * 33 * 16;

__global__ __launch_bounds__(256, 1) void fold_kernel(const float* __restrict__ conv_w,
                                                      const float* __restrict__ lin_w) {
    extern __shared__ float4 sm4[];
    float4* lw4 = sm4;
    float4* cw4 = sm4 + 128 * 33;
    int k = blockIdx.x;
    const float4* lws = (const float4*)lin_w;
    const float4* cws = (const float4*)(conv_w + (size_t)k * CH * CH);
    for (int q = threadIdx.x; q < 128 * 32; q += 256) {
        int row = q >> 5, c = q & 31;
        lw4[row * 33 + c] = lws[q];
        cw4[row * 33 + c] = cws[q];
    }
    __syncthreads();
    int tx = threadIdx.x & 15, ty = threadIdx.x >> 4;
    float acc[8][8];
#pragma unroll
    for (int o = 0; o < 8; o++)
#pragma unroll
        for (int i = 0; i < 8; i++) acc[o][i] = 0.f;
    for (int jc = 0; jc < 32; ++jc) {
        float4 a[8], b[8];
#pragma unroll
        for (int o = 0; o < 8; o++) a[o] = lw4[(ty + o * 16) * 33 + jc];
#pragma unroll
        for (int i = 0; i < 8; i++) b[i] = cw4[(tx + i * 16) * 33 + jc];
#pragma unroll
        for (int o = 0; o < 8; o++)
#pragma unroll
            for (int i = 0; i < 8; i++)
                acc[o][i] += a[o].x * b[i].x + a[o].y * b[i].y + a[o].z * b[i].z + a[o].w * b[i].w;
    }
#pragma unroll
    for (int o = 0; o < 8; o++) {
        int oc = ty + o * 16;
#pragma unroll
        for (int i = 0; i < 8; i++) {
            int ic = tx + i * 16;
            g_Wm[(((size_t)k * 4 + (ic >> 5)) * 128 + oc) * 36 + (ic & 31)] =
                __uint_as_float(tf32r(acc[o][i]));
        }
    }
}

__global__ void bias_kernel(const float* __restrict__ lin_w, const float* __restrict__ conv_b,
                            const float* __restrict__ lin_b) {
    int c = threadIdx.x;
    float s = lin_b[c];
    for (int j = 0; j < CH; j++) s += lin_w[c * CH + j] * conv_b[j];
    g_fb[c] = s;
}

// ---------------------------- main fused kernel ----------------------------
// SMEM: mbar[3] | fb/lnw/lnb | 3 stage bufs {A 18KB | B 18KB}, 144B rows
static constexpr int MBAR_OFF = 0;   // 3 x 8B
static constexpr int FB_OFF = 64;
static constexpr int LNW_OFF = 576;
static constexpr int LNB_OFF = 1088;
static constexpr int STAGE_OFF = 2048;
static constexpr int MAIN_SMEM = STAGE_OFF + NSTAGE * STAGE_BYTES;  // 112640

__global__ __launch_bounds__(256, 2) void ptv3_main(const float* __restrict__ ln_w,
                                                    const float* __restrict__ ln_b,
                                                    float* __restrict__ out, int n) {
    extern __shared__ char sm[];
    float* s_fb = (float*)(sm + FB_OFF);
    float* s_lnw = (float*)(sm + LNW_OFF);
    float* s_lnb = (float*)(sm + LNB_OFF);
    char* s_stage = sm + STAGE_OFF;

    const int tid = threadIdx.x;
    const int base = blockIdx.x * TILE_M;
    const int lane = tid & 31, wid = tid >> 5;
    const int quad = lane >> 2, four = lane & 3;
    const int wm = (wid & 3) * 32;   // 4 M-groups x 32 rows
    const int wn = (wid >> 2) * 64;  // 2 N-groups x 64 cols

    const uint32_t smb = smem_u32(sm);
    const uint32_t mbar0 = smb + MBAR_OFF;
    const uint32_t stage_u32 = smb + STAGE_OFF;

    if (tid < CH) {
        s_fb[tid] = g_fb[tid];
        s_lnw[tid] = ln_w[tid];
        s_lnb[tid] = ln_b[tid];
    }
    if (tid == 0) {
        MBAR_INIT(mbar0 + 0, 1);
        MBAR_INIT(mbar0 + 8, 1);
        MBAR_INIT(mbar0 + 16, 1);
    }
    __syncthreads();
    if (tid == 0) {
        MBAR_EXPECT(mbar0 + 0, TX_BYTES);
        MBAR_EXPECT(mbar0 + 8, TX_BYTES);
    }
    __syncthreads();

    // issue one stage: threads 0..127 each one A row (128B), thread 128 B tile
    auto issue_stage = [&](int s) {
        const int k = s >> 2, q = s & 3, buf = s % NSTAGE;
        const uint32_t off = (uint32_t)buf * STAGE_BYTES;
        const uint32_t mb = mbar0 + 8u * (uint32_t)buf;
        if (tid < 128) {
            int idx = g_idxT[(size_t)k * MAXN2 + base + tid];
            const float* src = g_feats + (size_t)idx * CH + q * 32;
            bulk_g2s(stage_u32 + off + (uint32_t)tid * ROWB, src, 128, mb);
        } else if (tid == 128) {
            const float* src = g_Wm + ((size_t)k * 4 + q) * (128 * 36);
            bulk_g2s(stage_u32 + off + A_BYTES, src, B_BYTES, mb);
        }
    };

    if (tid <= 128) FENCE_ASYNC();
    issue_stage(0);
    issue_stage(1);

    // LDSM lane addressing (144B row stride; conflict-free: bank=4(r+c)%32)
    const int a_r0 = wm + ((lane >> 3) & 1) * 8 + (lane & 7);  // + tm*16
    const int a_hi = lane >> 4;
    const int b_n0 = wn + (lane >> 4) * 8 + (lane & 7);        // + p*16
    const int b_kn = (lane >> 3) & 1;

    float acc[2][8][4];
#pragma unroll
    for (int tm = 0; tm < 2; tm++)
#pragma unroll
        for (int tn = 0; tn < 8; tn++)
#pragma unroll
            for (int i = 0; i < 4; i++) acc[tm][tn][i] = 0.f;

    for (int s = 0; s < NSTAGES_TOTAL; ++s) {
        MBAR_WAIT(mbar0 + 8u * (uint32_t)(s % NSTAGE), (uint32_t)((s / NSTAGE) & 1));
        if (tid == 0 && s + 2 < NSTAGES_TOTAL)
            MBAR_EXPECT(mbar0 + 8u * (uint32_t)((s + 2) % NSTAGE), TX_BYTES);
        __syncthreads();  // all warps done with compute(s-1); expects ordered
        if (s + 2 < NSTAGES_TOTAL) {
            if (tid <= 128) FENCE_ASYNC();
            issue_stage(s + 2);
        }

        const uint32_t Ab = stage_u32 + (uint32_t)(s % NSTAGE) * STAGE_BYTES;
        const uint32_t Bb = Ab + A_BYTES;

#pragma unroll
        for (int kt = 0; kt < 4; ++kt) {
            uint32_t bf[8][2];
#pragma unroll
            for (int p = 0; p < 4; ++p) {
                const int nr = b_n0 + p * 16;
                const int c = kt * 2 + b_kn;
                ldsm_x4(bf[2 * p][0], bf[2 * p][1], bf[2 * p + 1][0], bf[2 * p + 1][1],
                        Bb + (uint32_t)nr * ROWB + ((uint32_t)c << 4));
            }
#pragma unroll
            for (int tm = 0; tm < 2; ++tm) {
                const int ar = a_r0 + tm * 16;
                const int c = kt * 2 + a_hi;
                uint32_t a0, a1, a2, a3;
                ldsm_x4(a0, a1, a2, a3, Ab + (uint32_t)ar * ROWB + ((uint32_t)c << 4));
#pragma unroll
                for (int tn = 0; tn < 8; ++tn)
                    mma_tf32(acc[tm][tn], a0, a1, a2, a3, bf[tn][0], bf[tn][1]);
            }
        }
    }

    // ---- epilogue: stage accumulators, LayerNorm, store ----
    __syncthreads();
    float* stg = (float*)s_stage;  // [128][132] = 67584B fits stage region
#pragma unroll
    for (int tm = 0; tm < 2; ++tm) {
        const int r = wm + tm * 16 + quad;
#pragma unroll
        for (int tn = 0; tn < 8; ++tn) {
            const int col = wn + tn * 8 + 2 * four;
            stg[r * 132 + col] = acc[tm][tn][0];
            stg[r * 132 + col + 1] = acc[tm][tn][1];
            stg[(r + 8) * 132 + col] = acc[tm][tn][2];
            stg[(r + 8) * 132 + col + 1] = acc[tm][tn][3];
        }
    }
    __syncthreads();

    const int row = tid >> 1, half = tid & 1;
    const int c0 = half * 64;
    float sum = 0.f, sq = 0.f;
#pragma unroll 16
    for (int i = 0; i < 64; ++i) {
        float v = stg[row * 132 + c0 + i] + s_fb[c0 + i];
        sum += v;
        sq += v * v;
    }
    sum += __shfl_xor_sync(0xFFFFFFFFu, sum, 1);
    sq += __shfl_xor_sync(0xFFFFFFFFu, sq, 1);
    const float mu = sum * (1.f / 128.f);
    const float var = sq * (1.f / 128.f) - mu * mu;
    const float rs = rsqrtf(var + 1e-5f);

    const int grow = base + row;
    if (grow < n) {
        float4* orow = (float4*)(out + (size_t)grow * CH + c0);
#pragma unroll
        for (int q = 0; q < 16; ++q) {
            float4 o;
            const int c = c0 + q * 4;
            o.x = (stg[row * 132 + c + 0] + s_fb[c + 0] - mu) * rs * s_lnw[c + 0] + s_lnb[c + 0];
            o.y = (stg[row * 132 + c + 1] + s_fb[c + 1] - mu) * rs * s_lnw[c + 1] + s_lnb[c + 1];
            o.z = (stg[row * 132 + c + 2] + s_fb[c + 2] - mu) * rs * s_lnw[c + 2] + s_lnb[c + 2];
            o.w = (stg[row * 132 + c + 3] + s_fb[c + 3] - mu) * rs * s_lnw[c + 3] + s_lnb[c + 3];
            orow[q] = o;
        }
    }
}

// ---------------------------- launcher -------------------------------------
extern "C" void kernel_launch(void* const* d_in, const int* in_sizes, int n_in,
                              void* d_out, int out_size) {
    const float* feats = (const float*)d_in[0];
    const int* nbr = (const int*)d_in[1];
    const float* conv_w = (const float*)d_in[2];
    const float* conv_b = (const float*)d_in[3];
    const float* lin_w = (const float*)d_in[4];
    const float* lin_b = (const float*)d_in[5];
    const float* ln_w = (const float*)d_in[6];
    const float* ln_b = (const float*)d_in[7];
    float* out = (float*)d_out;
    int n = in_sizes[0] / CH;

    cudaFuncSetAttribute(fold_kernel, cudaFuncAttributeMaxDynamicSharedMemorySize, FOLD_SMEM);
    cudaFuncSetAttribute(ptv3_main, cudaFuncAttributeMaxDynamicSharedMemorySize, MAIN_SMEM);

    int n4 = n * (CH / 4);
    preround_kernel<<<(n4 + 255) / 256, 256>>>((const float4*)feats, n4);
    idxt_kernel<<<(MAXN2 + 255) / 256, 256>>>(nbr, n);
    fold_kernel<<<KT, 256, FOLD_SMEM>>>(conv_w, lin_w);
    bias_kernel<<<1, CH>>>(lin_w, conv_b, lin_b);
    int grid = (n + TILE_M - 1) / TILE_M;
    ptv3_main<<<grid, 256, MAIN_SMEM>>>(ln_w, ln_b, out, n);
}

// round 13
// speedup vs baseline: 2.8253x; 1.7477x over previous
#include <cuda_runtime.h>
#include <cuda_fp16.h>
#include <cstdint>

// ============================================================================
// PTV3_CPE: sparse-conv(27-tap gather GEMM) + Linear + LayerNorm, fused.
// Plain-sm_103: mma.sync.m16n8k16.f16 (fp32 acc) + ldmatrix + cp.async.bulk.
// R12: fp16 math (same 11-bit significand as tf32), K=64 stages (54 total),
//      bulk-copy ring, 144B padded rows, 2 CTAs/SM.
// ============================================================================

#define CH 128
#define KT 27
#define TILE_M 128
#define NSTAGE 3
#define NSTAGES_TOTAL (2 * KT)  // (tap, K-half) stages = 54
#define MAXN 200000
#define MAXN2 200064  // padded to grid*TILE_M

#define ROWB 144                      // padded SMEM row stride (bytes)
#define A_BYTES (128 * ROWB)          // 18432 (128 rows x 64 fp16 + pad)
#define B_BYTES (128 * ROWB)          // 18432 (128 n-rows x 64 fp16 + pad)
#define STAGE_BYTES (A_BYTES + B_BYTES)
#define TX_BYTES (128 * 128 + B_BYTES)  // 16384 actual A + 18432 padded B

__device__ __half g_featsh[MAXN * CH];       // fp16 feats (51.2 MB bss)
__device__ __half g_Wmh[KT * 2 * 128 * 72];  // folded weights, padded rows [k][h][n][72]
__device__ int g_idxT[KT * MAXN2];           // transposed neighbor idx [k][voxel]
__device__ float g_fb[CH];                   // folded bias

// ---------------------------- helpers --------------------------------------
__device__ __forceinline__ uint32_t smem_u32(const void* p) {
    uint32_t a;
    asm("{ .reg .u64 t; cvta.to.shared.u64 t, %1; cvt.u32.u64 %0, t; }" : "=r"(a) : "l"(p));
    return a;
}
__device__ __forceinline__ void bulk_g2s(uint32_t dst, const void* src, uint32_t bytes,
                                         uint32_t mbar) {
    asm volatile(
        "cp.async.bulk.shared::cluster.global.mbarrier::complete_tx::bytes [%0], [%1], %2, [%3];"
        :: "r"(dst), "l"(src), "r"(bytes), "r"(mbar) : "memory");
}
#define MBAR_INIT(a, cnt) \
    asm volatile("mbarrier.init.shared.b64 [%0], %1;" :: "r"((uint32_t)(a)), "r"((uint32_t)(cnt)) : "memory")
#define MBAR_EXPECT(a, tx) \
    asm volatile("mbarrier.arrive.expect_tx.shared.b64 _, [%0], %1;" \
                 :: "r"((uint32_t)(a)), "r"((uint32_t)(tx)) : "memory")
#define MBAR_WAIT(a, par) do { \
    uint32_t _m = (uint32_t)(a); uint32_t _p = (uint32_t)(par); uint32_t _d; \
    asm volatile("{\n\t.reg .pred p;\n\t" \
        "mbarrier.try_wait.parity.acquire.cta.shared::cta.b64 p, [%1], %2;\n\t" \
        "selp.b32 %0, 1, 0, p;\n\t}" : "=r"(_d) : "r"(_m), "r"(_p) : "memory"); \
    if (!_d) { \
        asm volatile("{\n\t.reg .pred P1;\n\t" \
            "WL_%=:\n\t" \
            "mbarrier.try_wait.parity.acquire.cta.shared::cta.b64 P1, [%0], %1, 0x989680;\n\t" \
            "@P1 bra.uni WD_%=;\n\tbra.uni WL_%=;\n\tWD_%=:\n\t}" \
            :: "r"(_m), "r"(_p) : "memory"); \
    } \
} while (0)
#define FENCE_ASYNC() asm volatile("fence.proxy.async.shared::cta;" ::: "memory")

__device__ __forceinline__ void ldsm_x4(uint32_t& r0, uint32_t& r1, uint32_t& r2, uint32_t& r3,
                                        uint32_t addr) {
    asm volatile("ldmatrix.sync.aligned.m8n8.x4.shared.b16 {%0,%1,%2,%3}, [%4];"
                 : "=r"(r0), "=r"(r1), "=r"(r2), "=r"(r3) : "r"(addr));
}
__device__ __forceinline__ void mma_f16(float* d, uint32_t a0, uint32_t a1, uint32_t a2,
                                        uint32_t a3, uint32_t b0, uint32_t b1) {
    asm volatile(
        "mma.sync.aligned.m16n8k16.row.col.f32.f16.f16.f32 "
        "{%0,%1,%2,%3}, {%4,%5,%6,%7}, {%8,%9}, {%0,%1,%2,%3};"
        : "+f"(d[0]), "+f"(d[1]), "+f"(d[2]), "+f"(d[3])
        : "r"(a0), "r"(a1), "r"(a2), "r"(a3), "r"(b0), "r"(b1));
}

// ---------------------- one-time prep kernels ------------------------------
__global__ __launch_bounds__(256) void preround_kernel(const float4* __restrict__ in, int n4) {
    int i = blockIdx.x * 256 + threadIdx.x;
    if (i < n4) {
        float4 v = in[i];
        __half2* dst = (__half2*)(g_featsh + (size_t)i * 4);
        dst[0] = __floats2half2_rn(v.x, v.y);
        dst[1] = __floats2half2_rn(v.z, v.w);
    }
}

__global__ __launch_bounds__(256) void idxt_kernel(const int* __restrict__ nbr, int n) {
    int v = blockIdx.x * 256 + threadIdx.x;
    if (v < MAXN2) {
#pragma unroll 1
        for (int k = 0; k < KT; ++k)
            g_idxT[(size_t)k * MAXN2 + v] = (v < n) ? nbr[(size_t)v * KT + k] : 0;
    }
}

// g_Wmh[((k*2+h)*128 + oc)*72 + (ic&63)] = fp16(sum_j conv_w[k][ic][j]*lin_w[oc][j])
static constexpr int FOLD_SMEM = 2 * 128 * 33 * 16;

__global__ __launch_bounds__(256, 1) void fold_kernel(const float* __restrict__ conv_w,
                                                      const float* __restrict__ lin_w) {
    extern __shared__ float4 sm4[];
    float4* lw4 = sm4;
    float4* cw4 = sm4 + 128 * 33;
    int k = blockIdx.x;
    const float4* lws = (const float4*)lin_w;
    const float4* cws = (const float4*)(conv_w + (size_t)k * CH * CH);
    for (int q = threadIdx.x; q < 128 * 32; q += 256) {
        int row = q >> 5, c = q & 31;
        lw4[row * 33 + c] = lws[q];
        cw4[row * 33 + c] = cws[q];
    }
    __syncthreads();
    int tx = threadIdx.x & 15, ty = threadIdx.x >> 4;
    float acc[8][8];
#pragma unroll
    for (int o = 0; o < 8; o++)
#pragma unroll
        for (int i = 0; i < 8; i++) acc[o][i] = 0.f;
    for (int jc = 0; jc < 32; ++jc) {
        float4 a[8], b[8];
#pragma unroll
        for (int o = 0; o < 8; o++) a[o] = lw4[(ty + o * 16) * 33 + jc];
#pragma unroll
        for (int i = 0; i < 8; i++) b[i] = cw4[(tx + i * 16) * 33 + jc];
#pragma unroll
        for (int o = 0; o < 8; o++)
#pragma unroll
            for (int i = 0; i < 8; i++)
                acc[o][i] += a[o].x * b[i].x + a[o].y * b[i].y + a[o].z * b[i].z + a[o].w * b[i].w;
    }
#pragma unroll
    for (int o = 0; o < 8; o++) {
        int oc = ty + o * 16;
#pragma unroll
        for (int i = 0; i < 8; i++) {
            int ic = tx + i * 16;
            g_Wmh[(((size_t)k * 2 + (ic >> 6)) * 128 + oc) * 72 + (ic & 63)] =
                __float2half_rn(acc[o][i]);
        }
    }
}

__global__ void bias_kernel(const float* __restrict__ lin_w, const float* __restrict__ conv_b,
                            const float* __restrict__ lin_b) {
    int c = threadIdx.x;
    float s = lin_b[c];
    for (int j = 0; j < CH; j++) s += lin_w[c * CH + j] * conv_b[j];
    g_fb[c] = s;
}

// ---------------------------- main fused kernel ----------------------------
// SMEM: mbar[3] | fb/lnw/lnb | 3 stage bufs {A 18KB | B 18KB}, 144B rows
static constexpr int MBAR_OFF = 0;
static constexpr int FB_OFF = 64;
static constexpr int LNW_OFF = 576;
static constexpr int LNB_OFF = 1088;
static constexpr int STAGE_OFF = 2048;
static constexpr int MAIN_SMEM = STAGE_OFF + NSTAGE * STAGE_BYTES;  // 112640

__global__ __launch_bounds__(256, 2) void ptv3_main(const float* __restrict__ ln_w,
                                                    const float* __restrict__ ln_b,
                                                    float* __restrict__ out, int n) {
    extern __shared__ char sm[];
    float* s_fb = (float*)(sm + FB_OFF);
    float* s_lnw = (float*)(sm + LNW_OFF);
    float* s_lnb = (float*)(sm + LNB_OFF);
    char* s_stage = sm + STAGE_OFF;

    const int tid = threadIdx.x;
    const int base = blockIdx.x * TILE_M;
    const int lane = tid & 31, wid = tid >> 5;
    const int quad = lane >> 2, four = lane & 3;
    const int wm = (wid & 3) * 32;   // 4 M-groups x 32 rows
    const int wn = (wid >> 2) * 64;  // 2 N-groups x 64 cols

    const uint32_t smb = smem_u32(sm);
    const uint32_t mbar0 = smb + MBAR_OFF;
    const uint32_t stage_u32 = smb + STAGE_OFF;

    if (tid < CH) {
        s_fb[tid] = g_fb[tid];
        s_lnw[tid] = ln_w[tid];
        s_lnb[tid] = ln_b[tid];
    }
    if (tid == 0) {
        MBAR_INIT(mbar0 + 0, 1);
        MBAR_INIT(mbar0 + 8, 1);
        MBAR_INIT(mbar0 + 16, 1);
    }
    __syncthreads();
    if (tid == 0) {
        MBAR_EXPECT(mbar0 + 0, TX_BYTES);
        MBAR_EXPECT(mbar0 + 8, TX_BYTES);
    }
    __syncthreads();

    // issue one stage: threads 0..127 one A row (128B = 64 fp16), thr 128 B tile
    auto issue_stage = [&](int s) {
        const int k = s >> 1, h = s & 1, buf = s % NSTAGE;
        const uint32_t off = (uint32_t)buf * STAGE_BYTES;
        const uint32_t mb = mbar0 + 8u * (uint32_t)buf;
        if (tid < 128) {
            int idx = g_idxT[(size_t)k * MAXN2 + base + tid];
            const __half* src = g_featsh + (size_t)idx * CH + h * 64;
            bulk_g2s(stage_u32 + off + (uint32_t)tid * ROWB, src, 128, mb);
        } else if (tid == 128) {
            const __half* src = g_Wmh + ((size_t)k * 2 + h) * (128 * 72);
            bulk_g2s(stage_u32 + off + A_BYTES, src, B_BYTES, mb);
        }
    };

    if (tid <= 128) FENCE_ASYNC();
    issue_stage(0);
    issue_stage(1);

    // LDSM lane addressing (m16n8k16 fragments, 144B rows, conflict-free)
    const int a_r0 = wm + ((lane >> 3) & 1) * 8 + (lane & 7);  // + tm*16
    const int a_hi = lane >> 4;                                 // k-half (16B)
    const int b_n0 = wn + (lane >> 4) * 8 + (lane & 7);         // + p*16
    const int b_kn = (lane >> 3) & 1;                           // k-half (16B)

    float acc[2][8][4];
#pragma unroll
    for (int tm = 0; tm < 2; tm++)
#pragma unroll
        for (int tn = 0; tn < 8; tn++)
#pragma unroll
            for (int i = 0; i < 4; i++) acc[tm][tn][i] = 0.f;

    for (int s = 0; s < NSTAGES_TOTAL; ++s) {
        MBAR_WAIT(mbar0 + 8u * (uint32_t)(s % NSTAGE), (uint32_t)((s / NSTAGE) & 1));
        if (tid == 0 && s + 2 < NSTAGES_TOTAL)
            MBAR_EXPECT(mbar0 + 8u * (uint32_t)((s + 2) % NSTAGE), TX_BYTES);
        __syncthreads();
        if (s + 2 < NSTAGES_TOTAL) {
            if (tid <= 128) FENCE_ASYNC();
            issue_stage(s + 2);
        }

        const uint32_t Ab = stage_u32 + (uint32_t)(s % NSTAGE) * STAGE_BYTES;
        const uint32_t Bb = Ab + A_BYTES;

#pragma unroll
        for (int kt = 0; kt < 4; ++kt) {  // K=64 -> 4 steps of k16 (32B each)
            uint32_t bf[8][2];
#pragma unroll
            for (int p = 0; p < 4; ++p) {
                const int nr = b_n0 + p * 16;
                ldsm_x4(bf[2 * p][0], bf[2 * p][1], bf[2 * p + 1][0], bf[2 * p + 1][1],
                        Bb + (uint32_t)nr * ROWB + (uint32_t)(kt * 32 + b_kn * 16));
            }
#pragma unroll
            for (int tm = 0; tm < 2; ++tm) {
                const int ar = a_r0 + tm * 16;
                uint32_t a0, a1, a2, a3;
                ldsm_x4(a0, a1, a2, a3,
                        Ab + (uint32_t)ar * ROWB + (uint32_t)(kt * 32 + a_hi * 16));
#pragma unroll
                for (int tn = 0; tn < 8; ++tn)
                    mma_f16(acc[tm][tn], a0, a1, a2, a3, bf[tn][0], bf[tn][1]);
            }
        }
    }

    // ---- epilogue: stage accumulators, LayerNorm, store ----
    __syncthreads();
    float* stg = (float*)s_stage;  // [128][132] = 67584B fits stage region
#pragma unroll
    for (int tm = 0; tm < 2; ++tm) {
        const int r = wm + tm * 16 + quad;
#pragma unroll
        for (int tn = 0; tn < 8; ++tn) {
            const int col = wn + tn * 8 + 2 * four;
            stg[r * 132 + col] = acc[tm][tn][0];
            stg[r * 132 + col + 1] = acc[tm][tn][1];
            stg[(r + 8) * 132 + col] = acc[tm][tn][2];
            stg[(r + 8) * 132 + col + 1] = acc[tm][tn][3];
        }
    }
    __syncthreads();

    const int row = tid >> 1, half = tid & 1;
    const int c0 = half * 64;
    float sum = 0.f, sq = 0.f;
#pragma unroll 16
    for (int i = 0; i < 64; ++i) {
        float v = stg[row * 132 + c0 + i] + s_fb[c0 + i];
        sum += v;
        sq += v * v;
    }
    sum += __shfl_xor_sync(0xFFFFFFFFu, sum, 1);
    sq += __shfl_xor_sync(0xFFFFFFFFu, sq, 1);
    const float mu = sum * (1.f / 128.f);
    const float var = sq * (1.f / 128.f) - mu * mu;
    const float rs = rsqrtf(var + 1e-5f);

    const int grow = base + row;
    if (grow < n) {
        float4* orow = (float4*)(out + (size_t)grow * CH + c0);
#pragma unroll
        for (int q = 0; q < 16; ++q) {
            float4 o;
            const int c = c0 + q * 4;
            o.x = (stg[row * 132 + c + 0] + s_fb[c + 0] - mu) * rs * s_lnw[c + 0] + s_lnb[c + 0];
            o.y = (stg[row * 132 + c + 1] + s_fb[c + 1] - mu) * rs * s_lnw[c + 1] + s_lnb[c + 1];
            o.z = (stg[row * 132 + c + 2] + s_fb[c + 2] - mu) * rs * s_lnw[c + 2] + s_lnb[c + 2];
            o.w = (stg[row * 132 + c + 3] + s_fb[c + 3] - mu) * rs * s_lnw[c + 3] + s_lnb[c + 3];
            orow[q] = o;
        }
    }
}

// ---------------------------- launcher -------------------------------------
extern "C" void kernel_launch(void* const* d_in, const int* in_sizes, int n_in,
                              void* d_out, int out_size) {
    const float* feats = (const float*)d_in[0];
    const int* nbr = (const int*)d_in[1];
    const float* conv_w = (const float*)d_in[2];
    const float* conv_b = (const float*)d_in[3];
    const float* lin_w = (const float*)d_in[4];
    const float* lin_b = (const float*)d_in[5];
    const float* ln_w = (const float*)d_in[6];
    const float* ln_b = (const float*)d_in[7];
    float* out = (float*)d_out;
    int n = in_sizes[0] / CH;

    cudaFuncSetAttribute(fold_kernel, cudaFuncAttributeMaxDynamicSharedMemorySize, FOLD_SMEM);
    cudaFuncSetAttribute(ptv3_main, cudaFuncAttributeMaxDynamicSharedMemorySize, MAIN_SMEM);

    int n4 = n * (CH / 4);
    preround_kernel<<<(n4 + 255) / 256, 256>>>((const float4*)feats, n4);
    idxt_kernel<<<(MAXN2 + 255) / 256, 256>>>(nbr, n);
    fold_kernel<<<KT, 256, FOLD_SMEM>>>(conv_w, lin_w);
    bias_kernel<<<1, CH>>>(lin_w, conv_b, lin_b);
    int grid = (n + TILE_M - 1) / TILE_M;
    ptv3_main<<<grid, 256, MAIN_SMEM>>>(ln_w, ln_b, out, n);
}

// round 14
// speedup vs baseline: 2.8355x; 1.0036x over previous
#include <cuda_runtime.h>
#include <cuda_fp16.h>
#include <cstdint>

// ============================================================================
// PTV3_CPE: sparse-conv(27-tap gather GEMM) + Linear + LayerNorm, fused.
// Plain-sm_103: mma.sync.m16n8k16.f16 (fp32 acc) + ldmatrix + cp.async.bulk.
// R12: fp16 math (same 11-bit significand as tf32), K=64 stages (54 total),
//      bulk-copy ring, 144B padded rows, 2 CTAs/SM.
// ============================================================================

#define CH 128
#define KT 27
#define TILE_M 128
#define NSTAGE 3
#define NSTAGES_TOTAL (2 * KT)  // (tap, K-half) stages = 54
#define MAXN 200000
#define MAXN2 200064  // padded to grid*TILE_M

#define ROWB 144                      // padded SMEM row stride (bytes)
#define A_BYTES (128 * ROWB)          // 18432 (128 rows x 64 fp16 + pad)
#define B_BYTES (128 * ROWB)          // 18432 (128 n-rows x 64 fp16 + pad)
#define STAGE_BYTES (A_BYTES + B_BYTES)
#define TX_BYTES (128 * 128 + B_BYTES)  // 16384 actual A + 18432 padded B

__device__ __half g_featsh[MAXN * CH];       // fp16 feats (51.2 MB bss)
__device__ __half g_Wmh[KT * 2 * 128 * 72];  // folded weights, padded rows [k][h][n][72]
__device__ int g_idxT[KT * MAXN2];           // transposed neighbor idx [k][voxel]
__device__ float g_fb[CH];                   // folded bias

// ---------------------------- helpers --------------------------------------
__device__ __forceinline__ uint32_t smem_u32(const void* p) {
    uint32_t a;
    asm("{ .reg .u64 t; cvta.to.shared.u64 t, %1; cvt.u32.u64 %0, t; }" : "=r"(a) : "l"(p));
    return a;
}
__device__ __forceinline__ void bulk_g2s(uint32_t dst, const void* src, uint32_t bytes,
                                         uint32_t mbar) {
    asm volatile(
        "cp.async.bulk.shared::cluster.global.mbarrier::complete_tx::bytes [%0], [%1], %2, [%3];"
        :: "r"(dst), "l"(src), "r"(bytes), "r"(mbar) : "memory");
}
#define MBAR_INIT(a, cnt) \
    asm volatile("mbarrier.init.shared.b64 [%0], %1;" :: "r"((uint32_t)(a)), "r"((uint32_t)(cnt)) : "memory")
#define MBAR_EXPECT(a, tx) \
    asm volatile("mbarrier.arrive.expect_tx.shared.b64 _, [%0], %1;" \
                 :: "r"((uint32_t)(a)), "r"((uint32_t)(tx)) : "memory")
#define MBAR_WAIT(a, par) do { \
    uint32_t _m = (uint32_t)(a); uint32_t _p = (uint32_t)(par); uint32_t _d; \
    asm volatile("{\n\t.reg .pred p;\n\t" \
        "mbarrier.try_wait.parity.acquire.cta.shared::cta.b64 p, [%1], %2;\n\t" \
        "selp.b32 %0, 1, 0, p;\n\t}" : "=r"(_d) : "r"(_m), "r"(_p) : "memory"); \
    if (!_d) { \
        asm volatile("{\n\t.reg .pred P1;\n\t" \
            "WL_%=:\n\t" \
            "mbarrier.try_wait.parity.acquire.cta.shared::cta.b64 P1, [%0], %1, 0x989680;\n\t" \
            "@P1 bra.uni WD_%=;\n\tbra.uni WL_%=;\n\tWD_%=:\n\t}" \
            :: "r"(_m), "r"(_p) : "memory"); \
    } \
} while (0)
#define FENCE_ASYNC() asm volatile("fence.proxy.async.shared::cta;" ::: "memory")

__device__ __forceinline__ void ldsm_x4(uint32_t& r0, uint32_t& r1, uint32_t& r2, uint32_t& r3,
                                        uint32_t addr) {
    asm volatile("ldmatrix.sync.aligned.m8n8.x4.shared.b16 {%0,%1,%2,%3}, [%4];"
                 : "=r"(r0), "=r"(r1), "=r"(r2), "=r"(r3) : "r"(addr));
}
__device__ __forceinline__ void mma_f16(float* d, uint32_t a0, uint32_t a1, uint32_t a2,
                                        uint32_t a3, uint32_t b0, uint32_t b1) {
    asm volatile(
        "mma.sync.aligned.m16n8k16.row.col.f32.f16.f16.f32 "
        "{%0,%1,%2,%3}, {%4,%5,%6,%7}, {%8,%9}, {%0,%1,%2,%3};"
        : "+f"(d[0]), "+f"(d[1]), "+f"(d[2]), "+f"(d[3])
        : "r"(a0), "r"(a1), "r"(a2), "r"(a3), "r"(b0), "r"(b1));
}

// ---------------------- one-time prep kernels ------------------------------
__global__ __launch_bounds__(256) void preround_kernel(const float4* __restrict__ in, int n4) {
    int i = blockIdx.x * 256 + threadIdx.x;
    if (i < n4) {
        float4 v = in[i];
        __half2* dst = (__half2*)(g_featsh + (size_t)i * 4);
        dst[0] = __floats2half2_rn(v.x, v.y);
        dst[1] = __floats2half2_rn(v.z, v.w);
    }
}

__global__ __launch_bounds__(256) void idxt_kernel(const int* __restrict__ nbr, int n) {
    int v = blockIdx.x * 256 + threadIdx.x;
    if (v < MAXN2) {
#pragma unroll 1
        for (int k = 0; k < KT; ++k)
            g_idxT[(size_t)k * MAXN2 + v] = (v < n) ? nbr[(size_t)v * KT + k] : 0;
    }
}

// g_Wmh[((k*2+h)*128 + oc)*72 + (ic&63)] = fp16(sum_j conv_w[k][ic][j]*lin_w[oc][j])
static constexpr int FOLD_SMEM = 2 * 128 * 33 * 16;

__global__ __launch_bounds__(256, 1) void fold_kernel(const float* __restrict__ conv_w,
                                                      const float* __restrict__ lin_w) {
    extern __shared__ float4 sm4[];
    float4* lw4 = sm4;
    float4* cw4 = sm4 + 128 * 33;
    int k = blockIdx.x;
    const float4* lws = (const float4*)lin_w;
    const float4* cws = (const float4*)(conv_w + (size_t)k * CH * CH);
    for (int q = threadIdx.x; q < 128 * 32; q += 256) {
        int row = q >> 5, c = q & 31;
        lw4[row * 33 + c] = lws[q];
        cw4[row * 33 + c] = cws[q];
    }
    __syncthreads();
    int tx = threadIdx.x & 15, ty = threadIdx.x >> 4;
    float acc[8][8];
#pragma unroll
    for (int o = 0; o < 8; o++)
#pragma unroll
        for (int i = 0; i < 8; i++) acc[o][i] = 0.f;
    for (int jc = 0; jc < 32; ++jc) {
        float4 a[8], b[8];
#pragma unroll
        for (int o = 0; o < 8; o++) a[o] = lw4[(ty + o * 16) * 33 + jc];
#pragma unroll
        for (int i = 0; i < 8; i++) b[i] = cw4[(tx + i * 16) * 33 + jc];
#pragma unroll
        for (int o = 0; o < 8; o++)
#pragma unroll
            for (int i = 0; i < 8; i++)
                acc[o][i] += a[o].x * b[i].x + a[o].y * b[i].y + a[o].z * b[i].z + a[o].w * b[i].w;
    }
#pragma unroll
    for (int o = 0; o < 8; o++) {
        int oc = ty + o * 16;
#pragma unroll
        for (int i = 0; i < 8; i++) {
            int ic = tx + i * 16;
            g_Wmh[(((size_t)k * 2 + (ic >> 6)) * 128 + oc) * 72 + (ic & 63)] =
                __float2half_rn(acc[o][i]);
        }
    }
}

__global__ void bias_kernel(const float* __restrict__ lin_w, const float* __restrict__ conv_b,
                            const float* __restrict__ lin_b) {
    int c = threadIdx.x;
    float s = lin_b[c];
    for (int j = 0; j < CH; j++) s += lin_w[c * CH + j] * conv_b[j];
    g_fb[c] = s;
}

// ---------------------------- main fused kernel ----------------------------
// SMEM: mbar[3] | fb/lnw/lnb | 3 stage bufs {A 18KB | B 18KB}, 144B rows
static constexpr int MBAR_OFF = 0;
static constexpr int FB_OFF = 64;
static constexpr int LNW_OFF = 576;
static constexpr int LNB_OFF = 1088;
static constexpr int STAGE_OFF = 2048;
static constexpr int MAIN_SMEM = STAGE_OFF + NSTAGE * STAGE_BYTES;  // 112640

__global__ __launch_bounds__(256, 2) void ptv3_main(const float* __restrict__ ln_w,
                                                    const float* __restrict__ ln_b,
                                                    float* __restrict__ out, int n) {
    extern __shared__ char sm[];
    float* s_fb = (float*)(sm + FB_OFF);
    float* s_lnw = (float*)(sm + LNW_OFF);
    float* s_lnb = (float*)(sm + LNB_OFF);
    char* s_stage = sm + STAGE_OFF;

    const int tid = threadIdx.x;
    const int base = blockIdx.x * TILE_M;
    const int lane = tid & 31, wid = tid >> 5;
    const int quad = lane >> 2, four = lane & 3;
    const int wm = (wid & 3) * 32;   // 4 M-groups x 32 rows
    const int wn = (wid >> 2) * 64;  // 2 N-groups x 64 cols

    const uint32_t smb = smem_u32(sm);
    const uint32_t mbar0 = smb + MBAR_OFF;
    const uint32_t stage_u32 = smb + STAGE_OFF;

    if (tid < CH) {
        s_fb[tid] = g_fb[tid];
        s_lnw[tid] = ln_w[tid];
        s_lnb[tid] = ln_b[tid];
    }
    if (tid == 0) {
        MBAR_INIT(mbar0 + 0, 1);
        MBAR_INIT(mbar0 + 8, 1);
        MBAR_INIT(mbar0 + 16, 1);
    }
    __syncthreads();
    if (tid == 0) {
        MBAR_EXPECT(mbar0 + 0, TX_BYTES);
        MBAR_EXPECT(mbar0 + 8, TX_BYTES);
    }
    __syncthreads();

    // issue one stage: threads 0..127 one A row (128B = 64 fp16), thr 128 B tile
    auto issue_stage = [&](int s) {
        const int k = s >> 1, h = s & 1, buf = s % NSTAGE;
        const uint32_t off = (uint32_t)buf * STAGE_BYTES;
        const uint32_t mb = mbar0 + 8u * (uint32_t)buf;
        if (tid < 128) {
            int idx = g_idxT[(size_t)k * MAXN2 + base + tid];
            const __half* src = g_featsh + (size_t)idx * CH + h * 64;
            bulk_g2s(stage_u32 + off + (uint32_t)tid * ROWB, src, 128, mb);
        } else if (tid == 128) {
            const __half* src = g_Wmh + ((size_t)k * 2 + h) * (128 * 72);
            bulk_g2s(stage_u32 + off + A_BYTES, src, B_BYTES, mb);
        }
    };

    if (tid <= 128) FENCE_ASYNC();
    issue_stage(0);
    issue_stage(1);

    // LDSM lane addressing (m16n8k16 fragments, 144B rows, conflict-free)
    const int a_r0 = wm + ((lane >> 3) & 1) * 8 + (lane & 7);  // + tm*16
    const int a_hi = lane >> 4;                                 // k-half (16B)
    const int b_n0 = wn + (lane >> 4) * 8 + (lane & 7);         // + p*16
    const int b_kn = (lane >> 3) & 1;                           // k-half (16B)

    float acc[2][8][4];
#pragma unroll
    for (int tm = 0; tm < 2; tm++)
#pragma unroll
        for (int tn = 0; tn < 8; tn++)
#pragma unroll
            for (int i = 0; i < 4; i++) acc[tm][tn][i] = 0.f;

    for (int s = 0; s < NSTAGES_TOTAL; ++s) {
        MBAR_WAIT(mbar0 + 8u * (uint32_t)(s % NSTAGE), (uint32_t)((s / NSTAGE) & 1));
        if (tid == 0 && s + 2 < NSTAGES_TOTAL)
            MBAR_EXPECT(mbar0 + 8u * (uint32_t)((s + 2) % NSTAGE), TX_BYTES);
        __syncthreads();
        if (s + 2 < NSTAGES_TOTAL) {
            if (tid <= 128) FENCE_ASYNC();
            issue_stage(s + 2);
        }

        const uint32_t Ab = stage_u32 + (uint32_t)(s % NSTAGE) * STAGE_BYTES;
        const uint32_t Bb = Ab + A_BYTES;

#pragma unroll
        for (int kt = 0; kt < 4; ++kt) {  // K=64 -> 4 steps of k16 (32B each)
            uint32_t bf[8][2];
#pragma unroll
            for (int p = 0; p < 4; ++p) {
                const int nr = b_n0 + p * 16;
                ldsm_x4(bf[2 * p][0], bf[2 * p][1], bf[2 * p + 1][0], bf[2 * p + 1][1],
                        Bb + (uint32_t)nr * ROWB + (uint32_t)(kt * 32 + b_kn * 16));
            }
#pragma unroll
            for (int tm = 0; tm < 2; ++tm) {
                const int ar = a_r0 + tm * 16;
                uint32_t a0, a1, a2, a3;
                ldsm_x4(a0, a1, a2, a3,
                        Ab + (uint32_t)ar * ROWB + (uint32_t)(kt * 32 + a_hi * 16));
#pragma unroll
                for (int tn = 0; tn < 8; ++tn)
                    mma_f16(acc[tm][tn], a0, a1, a2, a3, bf[tn][0], bf[tn][1]);
            }
        }
    }

    // ---- epilogue: stage accumulators, LayerNorm, store ----
    __syncthreads();
    float* stg = (float*)s_stage;  // [128][132] = 67584B fits stage region
#pragma unroll
    for (int tm = 0; tm < 2; ++tm) {
        const int r = wm + tm * 16 + quad;
#pragma unroll
        for (int tn = 0; tn < 8; ++tn) {
            const int col = wn + tn * 8 + 2 * four;
            stg[r * 132 + col] = acc[tm][tn][0];
            stg[r * 132 + col + 1] = acc[tm][tn][1];
            stg[(r + 8) * 132 + col] = acc[tm][tn][2];
            stg[(r + 8) * 132 + col + 1] = acc[tm][tn][3];
        }
    }
    __syncthreads();

    const int row = tid >> 1, half = tid & 1;
    const int c0 = half * 64;
    float sum = 0.f, sq = 0.f;
#pragma unroll 16
    for (int i = 0; i < 64; ++i) {
        float v = stg[row * 132 + c0 + i] + s_fb[c0 + i];
        sum += v;
        sq += v * v;
    }
    sum += __shfl_xor_sync(0xFFFFFFFFu, sum, 1);
    sq += __shfl_xor_sync(0xFFFFFFFFu, sq, 1);
    const float mu = sum * (1.f / 128.f);
    const float var = sq * (1.f / 128.f) - mu * mu;
    const float rs = rsqrtf(var + 1e-5f);

    const int grow = base + row;
    if (grow < n) {
        float4* orow = (float4*)(out + (size_t)grow * CH + c0);
#pragma unroll
        for (int q = 0; q < 16; ++q) {
            float4 o;
            const int c = c0 + q * 4;
            o.x = (stg[row * 132 + c + 0] + s_fb[c + 0] - mu) * rs * s_lnw[c + 0] + s_lnb[c + 0];
            o.y = (stg[row * 132 + c + 1] + s_fb[c + 1] - mu) * rs * s_lnw[c + 1] + s_lnb[c + 1];
            o.z = (stg[row * 132 + c + 2] + s_fb[c + 2] - mu) * rs * s_lnw[c + 2] + s_lnb[c + 2];
            o.w = (stg[row * 132 + c + 3] + s_fb[c + 3] - mu) * rs * s_lnw[c + 3] + s_lnb[c + 3];
            orow[q] = o;
        }
    }
}

// ---------------------------- launcher -------------------------------------
extern "C" void kernel_launch(void* const* d_in, const int* in_sizes, int n_in,
                              void* d_out, int out_size) {
    const float* feats = (const float*)d_in[0];
    const int* nbr = (const int*)d_in[1];
    const float* conv_w = (const float*)d_in[2];
    const float* conv_b = (const float*)d_in[3];
    const float* lin_w = (const float*)d_in[4];
    const float* lin_b = (const float*)d_in[5];
    const float* ln_w = (const float*)d_in[6];
    const float* ln_b = (const float*)d_in[7];
    float* out = (float*)d_out;
    int n = in_sizes[0] / CH;

    cudaFuncSetAttribute(fold_kernel, cudaFuncAttributeMaxDynamicSharedMemorySize, FOLD_SMEM);
    cudaFuncSetAttribute(ptv3_main, cudaFuncAttributeMaxDynamicSharedMemorySize, MAIN_SMEM);

    int n4 = n * (CH / 4);
    preround_kernel<<<(n4 + 255) / 256, 256>>>((const float4*)feats, n4);
    idxt_kernel<<<(MAXN2 + 255) / 256, 256>>>(nbr, n);
    fold_kernel<<<KT, 256, FOLD_SMEM>>>(conv_w, lin_w);
    bias_kernel<<<1, CH>>>(lin_w, conv_b, lin_b);
    int grid = (n + TILE_M - 1) / TILE_M;
    ptv3_main<<<grid, 256, MAIN_SMEM>>>(ln_w, ln_b, out, n);
}